// round 15
// baseline (speedup 1.0000x reference)
#include <cuda_runtime.h>
#include <cuda_fp16.h>
#include <cstdint>

// Problem constants
#define BB 2
#define TT 4096
#define EE 768
#define HH 12
#define DD 64
#define MM (BB * TT)        // 8192
#define N_QKV (3 * EE)      // 2304
#define KTOT 768
#define LOG2E 1.4426950408889634f

// Scratch (allocation-free rule: __device__ globals), all fp16
__device__ __half g_q[(size_t)BB * HH * TT * DD];   // [B,H,T,D], scaled 0.125*log2e
__device__ __half g_k[(size_t)BB * HH * TT * DD];   // [B,H,T,D]
__device__ __half g_v[(size_t)BB * HH * TT * DD];   // [B,H,T,D]
__device__ __half g_y[(size_t)BB * TT * EE];        // [B,T,E]
__device__ __half g_xt[(size_t)MM * EE];            // X as half
__device__ __half g_wta[(size_t)N_QKV * EE];        // W_attn^T [2304][768]
__device__ __half g_wtp[(size_t)EE * EE];           // W_proj^T [768][768]

// ---------------------------------------------------------------------------
// Helpers
// ---------------------------------------------------------------------------
__device__ __forceinline__ uint32_t smem_u32(const void* p) {
    uint32_t a;
    asm("{ .reg .u64 t; cvta.to.shared.u64 t, %1; cvt.u32.u64 %0, t; }"
        : "=r"(a) : "l"(p));
    return a;
}
__device__ __forceinline__ void cp16(uint32_t dst, const void* src) {
    asm volatile("cp.async.cg.shared.global [%0], [%1], 16;"
                 :: "r"(dst), "l"(src) : "memory");
}
__device__ __forceinline__ void cp_commit() {
    asm volatile("cp.async.commit_group;" ::: "memory");
}
template<int N> __device__ __forceinline__ void cp_wait() {
    asm volatile("cp.async.wait_group %0;" :: "n"(N) : "memory");
}
__device__ __forceinline__ uint32_t packh2(float a, float b) {
    __half2 h = __floats2half2_rn(a, b);
    return *(uint32_t*)&h;
}
__device__ __forceinline__ uint32_t ex2_h2(uint32_t x) {   // 2x half exp2, 1 MUFU
    uint32_t r;
    asm("ex2.approx.f16x2 %0, %1;" : "=r"(r) : "r"(x));
    return r;
}
// ldmatrix x4: four 8x8 b16 mats; lane l addresses row l%8 of mat l/8.
__device__ __forceinline__ void ldsm4(uint32_t* r, uint32_t addr) {
    asm volatile("ldmatrix.sync.aligned.m8n8.x4.shared.b16 {%0,%1,%2,%3}, [%4];"
                 : "=r"(r[0]), "=r"(r[1]), "=r"(r[2]), "=r"(r[3]) : "r"(addr));
}
// transposed variant: fragment = transpose of each stored 8x8 (b16)
__device__ __forceinline__ void ldsm4t(uint32_t* r, uint32_t addr) {
    asm volatile("ldmatrix.sync.aligned.m8n8.x4.trans.shared.b16 {%0,%1,%2,%3}, [%4];"
                 : "=r"(r[0]), "=r"(r[1]), "=r"(r[2]), "=r"(r[3]) : "r"(addr));
}

// mma.sync m16n8k16 f16 -> f32.
__device__ __forceinline__ void mma16(float* c, const uint32_t* a,
                                      uint32_t b0, uint32_t b1) {
    asm volatile(
        "mma.sync.aligned.m16n8k16.row.col.f32.f16.f16.f32 "
        "{%0,%1,%2,%3}, {%4,%5,%6,%7}, {%8,%9}, {%0,%1,%2,%3};\n"
        : "+f"(c[0]), "+f"(c[1]), "+f"(c[2]), "+f"(c[3])
        : "r"(a[0]), "r"(a[1]), "r"(a[2]), "r"(a[3]), "r"(b0), "r"(b1));
}

extern __shared__ uint32_t dyn_smem[];

// ---------------------------------------------------------------------------
// Merged prep kernel: one launch does X-convert + both weight transposes.
// Blocks [0, 3072): cvt X.  [3072, 4800): transpose W_attn.  [4800, 5376):
// transpose W_proj.  256 threads everywhere.
// ---------------------------------------------------------------------------
#define PREP_X_BLOCKS ((MM * EE) / (256 * 8))                 // 3072
#define PREP_WA_BLOCKS ((N_QKV / 32) * (EE / 32))             // 1728
#define PREP_WP_BLOCKS ((EE / 32) * (EE / 32))                // 576
#define PREP_BLOCKS (PREP_X_BLOCKS + PREP_WA_BLOCKS + PREP_WP_BLOCKS)

__global__ __launch_bounds__(256) void prep_kernel(
    const float* __restrict__ x, const float* __restrict__ Wa,
    const float* __restrict__ Wp,
    __half* __restrict__ xt, __half* __restrict__ wta, __half* __restrict__ wtp)
{
    __shared__ float t[32][33];
    const int bx = blockIdx.x;
    if (bx < PREP_X_BLOCKS) {
        size_t i = ((size_t)bx * 256 + threadIdx.x) * 8;
        float4 v0 = *(const float4*)&x[i];
        float4 v1 = *(const float4*)&x[i + 4];
        uint4 o;
        o.x = packh2(v0.x, v0.y);
        o.y = packh2(v0.z, v0.w);
        o.z = packh2(v1.x, v1.y);
        o.w = packh2(v1.z, v1.w);
        *(uint4*)&xt[i] = o;
        return;
    }
    // transpose branch: dst[n][k] = half(src[k][n])
    const float* src;
    __half* dst;
    int K, N, tb;
    if (bx < PREP_X_BLOCKS + PREP_WA_BLOCKS) {
        tb = bx - PREP_X_BLOCKS; src = Wa; dst = wta; K = EE; N = N_QKV;
    } else {
        tb = bx - PREP_X_BLOCKS - PREP_WA_BLOCKS; src = Wp; dst = wtp; K = EE; N = EE;
    }
    const int nblk = N / 32;
    const int n0 = (tb % nblk) * 32, k0 = (tb / nblk) * 32;
    const int tx = threadIdx.x & 31, ty = threadIdx.x >> 5;   // 32 x 8
#pragma unroll
    for (int j = 0; j < 4; j++)
        t[ty + j * 8][tx] = src[(size_t)(k0 + ty + j * 8) * N + n0 + tx];
    __syncthreads();
#pragma unroll
    for (int j = 0; j < 4; j++)
        dst[(size_t)(n0 + ty + j * 8) * K + k0 + tx] =
            __float2half_rn(t[tx][ty + j * 8]);
}

// ---------------------------------------------------------------------------
// QKV GEMM: BM128 x BN256, BK=128 halfs, 2-stage ring (halves barrier count
// vs BK=64/3-stage; one k-tile of compute overlaps each stage load).
// 512 threads = 16 warps in 4x4 grid of m32 x n64 tiles; register-level
// LDSM double buffering.  Epilogue staged through smem, coalesced scatter
// (q scaled by 0.125*log2e).
// ---------------------------------------------------------------------------
#define BKH2 128
#define NKT2 (KTOT / BKH2)      // 6
#define TW2 68                   // 64 data words + 4 pad (68 mod 32 == 4)
#define QA2 (128 * TW2)          // 8704 words
#define QB2 (256 * TW2)          // 17408 words
#define QST2 (QA2 + QB2)         // 26112 words per stage
#define QKV_SMEM (2 * QST2 * 4)  // 208896 B
#define CS_HW 264

__global__ __launch_bounds__(512, 1) void qkv_gemm_kernel(
    const __half* __restrict__ A, const __half* __restrict__ Bt,
    const float* __restrict__ bias)
{
    uint32_t* sm = dyn_smem;
    const uint32_t sb = smem_u32(sm);
    const int tid = threadIdx.x;
    const int warp = tid >> 5, lane = tid & 31;
    const int g = lane >> 2, tg = lane & 3;
    const int wm = warp >> 2, wn = warp & 3;      // 4 x 4 warp grid
    const int m0 = blockIdx.y * 128, n0 = blockIdx.x * 256;
    const int m0w = wm * 32, n0w = wn * 64;

    // cp.async staging: A 4 chunks + B 8 chunks of 16B per thread
    const int lrA = tid >> 2;                // A row 0..127 (16 chunks/row)
    const int cbA = (tid & 3) * 4;           // chunks cbA..cbA+3
    const int lrB = tid >> 1;                // B row 0..255
    const int cbB = (tid & 1) * 8;           // chunks cbB..cbB+7
    const __half* asrc0 = A + (size_t)(m0 + lrA) * KTOT + cbA * 8;
    const __half* bsrc0 = Bt + (size_t)(n0 + lrB) * KTOT + cbB * 8;
    const uint32_t adst0 = sb + (lrA * TW2 + cbA * 4) * 4;
    const uint32_t bdst0 = sb + (QA2 + lrB * TW2 + cbB * 4) * 4;

    // LDSM per-lane base offsets (within a stage)
    const int mt = lane >> 3, mr = lane & 7;
    uint32_t aoff[2];
#pragma unroll
    for (int mi = 0; mi < 2; mi++)
        aoff[mi] = ((m0w + mi * 16 + (mt & 1) * 8 + mr) * TW2 + (mt >> 1) * 4) * 4;
    uint32_t boff[4];
#pragma unroll
    for (int np = 0; np < 4; np++)
        boff[np] = (QA2 + (n0w + np * 16 + (mt >> 1) * 8 + mr) * TW2
                    + (mt & 1) * 4) * 4;

    float acc[2][8][4];
#pragma unroll
    for (int mi = 0; mi < 2; mi++)
#pragma unroll
        for (int nt = 0; nt < 8; nt++)
#pragma unroll
            for (int j = 0; j < 4; j++) acc[mi][nt][j] = 0.f;

    auto issue = [&](int i) {
        const int k0 = i * BKH2;
        const uint32_t so = (uint32_t)((i & 1) * QST2 * 4);
#pragma unroll
        for (int j = 0; j < 4; j++)
            cp16(adst0 + so + j * 16, asrc0 + k0 + j * 8);
#pragma unroll
        for (int j = 0; j < 8; j++)
            cp16(bdst0 + so + j * 16, bsrc0 + k0 + j * 8);
        cp_commit();
    };

    issue(0);
    for (int i = 0; i < NKT2; i++) {
        cp_wait<0>();
        __syncthreads();
        if (i + 1 < NKT2) issue(i + 1);   // writes other stage: readers done

        const uint32_t soff = sb + (uint32_t)((i & 1) * QST2 * 4);
        uint32_t af[2][2][4], bf[2][4][4];
        ldsm4(af[0][0], soff + aoff[0]);
        ldsm4(af[0][1], soff + aoff[1]);
#pragma unroll
        for (int np = 0; np < 4; np++) ldsm4(bf[0][np], soff + boff[np]);
#pragma unroll
        for (int ks = 0; ks < 8; ks++) {
            const int cur = ks & 1, nxt = cur ^ 1;
            if (ks < 7) {
                const uint32_t ko = soff + (ks + 1) * 32;
                ldsm4(af[nxt][0], ko + aoff[0]);
                ldsm4(af[nxt][1], ko + aoff[1]);
#pragma unroll
                for (int np = 0; np < 4; np++) ldsm4(bf[nxt][np], ko + boff[np]);
            }
#pragma unroll
            for (int np = 0; np < 4; np++) {
                mma16(acc[0][2 * np],     af[cur][0], bf[cur][np][0], bf[cur][np][1]);
                mma16(acc[0][2 * np + 1], af[cur][0], bf[cur][np][2], bf[cur][np][3]);
                mma16(acc[1][2 * np],     af[cur][1], bf[cur][np][0], bf[cur][np][1]);
                mma16(acc[1][2 * np + 1], af[cur][1], bf[cur][np][2], bf[cur][np][3]);
            }
        }
    }

    // Epilogue: stage C to smem (half, bias+scale), then coalesced scatter.
    __half* Cs = (__half*)sm;
    __syncthreads();
#pragma unroll
    for (int mi = 0; mi < 2; mi++)
#pragma unroll
        for (int hi = 0; hi < 2; hi++) {
            int lrow = m0w + mi * 16 + hi * 8 + g;
#pragma unroll
            for (int nt = 0; nt < 8; nt++) {
                int lcol = n0w + nt * 8 + 2 * tg;
                int gn = n0 + lcol;
                float v0 = acc[mi][nt][hi * 2] + bias[gn];
                float v1 = acc[mi][nt][hi * 2 + 1] + bias[gn + 1];
                float sc = (gn < EE) ? (0.125f * LOG2E) : 1.0f;
                *(__half2*)&Cs[lrow * CS_HW + lcol] =
                    __floats2half2_rn(v0 * sc, v1 * sc);
            }
        }
    __syncthreads();
#pragma unroll
    for (int it = 0; it < 8; it++) {
        int c = it * 512 + tid;            // 0..4095
        int row = c >> 5, seg = c & 31;
        uint4 v = *(uint4*)&Cs[row * CS_HW + seg * 8];
        int gm = m0 + row, gn = n0 + seg * 8;
        int bbv = gm >> 12, t = gm & (TT - 1);
        int part = gn / EE;
        int rem = gn - part * EE;
        int hh = rem >> 6, d = rem & 63;
        __half* dst = (part == 0) ? g_q : ((part == 1) ? g_k : g_v);
        *(uint4*)&dst[(((size_t)bbv * HH + hh) * TT + t) * DD + d] = v;
    }
}

// ---------------------------------------------------------------------------
// Output projection GEMM (best measured config): BM128 x BN128, BK=64,
// 512 threads = 16 warps in 8x2 grid of m16 x n64 tiles (384 blocks,
// good wave quantization).  3-stage pipeline + reg double buffering.
// ---------------------------------------------------------------------------
#define BKH 64
#define NKT (KTOT / BKH)        // 12
#define TILE_W 36
#define PHALF_ST (128 * TILE_W)             // 4608 words per A or B buffer
#define PSTAGE_WORDS (2 * PHALF_ST)         // 9216
#define PROJ_SMEM (3 * PSTAGE_WORDS * 4)    // 110592 B

__global__ __launch_bounds__(512, 1) void proj_gemm_kernel(
    const __half* __restrict__ A, const __half* __restrict__ Bt,
    const float* __restrict__ bias, float* __restrict__ out)
{
    uint32_t* sm = dyn_smem;
    const uint32_t sb = smem_u32(sm);
    const int tid = threadIdx.x;
    const int warp = tid >> 5, lane = tid & 31;
    const int g = lane >> 2, tg = lane & 3;
    const int wm = warp >> 1, wn = warp & 1;      // 8 x 2 warp grid
    const int m0 = blockIdx.y * 128, n0 = blockIdx.x * 128;
    const int m0w = wm * 16, n0w = wn * 64;

    const int lr = tid >> 2;
    const int cb = (tid & 3) * 2;
    const __half* asrc0 = A + (size_t)(m0 + lr) * KTOT + cb * 8;
    const __half* bsrc0 = Bt + (size_t)(n0 + lr) * KTOT + cb * 8;
    const uint32_t adst0 = sb + (lr * TILE_W + cb * 4) * 4;
    const uint32_t bdst0 = sb + (PHALF_ST + lr * TILE_W + cb * 4) * 4;

    const int mt = lane >> 3, mr = lane & 7;
    const uint32_t aoff =
        ((m0w + (mt & 1) * 8 + mr) * TILE_W + (mt >> 1) * 4) * 4;
    uint32_t boff[4];
#pragma unroll
    for (int np = 0; np < 4; np++)
        boff[np] = (PHALF_ST + (n0w + np * 16 + (mt >> 1) * 8 + mr) * TILE_W
                    + (mt & 1) * 4) * 4;

    float acc[8][4];
#pragma unroll
    for (int nt = 0; nt < 8; nt++)
#pragma unroll
        for (int j = 0; j < 4; j++) acc[nt][j] = 0.f;

    auto issue = [&](int i) {
        const int s = i % 3;
        const int k0 = i * BKH;
        const uint32_t so = (uint32_t)(s * PSTAGE_WORDS * 4);
        cp16(adst0 + so,      asrc0 + k0);
        cp16(adst0 + so + 16, asrc0 + k0 + 8);
        cp16(bdst0 + so,      bsrc0 + k0);
        cp16(bdst0 + so + 16, bsrc0 + k0 + 8);
        cp_commit();
    };

    issue(0);
    issue(1);
    for (int i = 0; i < NKT; i++) {
        if (i + 1 < NKT) cp_wait<1>(); else cp_wait<0>();
        __syncthreads();
        if (i + 2 < NKT) issue(i + 2);

        const uint32_t soff = sb + (uint32_t)((i % 3) * PSTAGE_WORDS * 4);
        uint32_t af[2][4], bf[2][4][4];
        ldsm4(af[0], soff + aoff);
#pragma unroll
        for (int np = 0; np < 4; np++) ldsm4(bf[0][np], soff + boff[np]);
#pragma unroll
        for (int ks = 0; ks < 4; ks++) {
            const int cur = ks & 1, nxt = cur ^ 1;
            if (ks < 3) {
                const uint32_t ko = soff + (ks + 1) * 32;
                ldsm4(af[nxt], ko + aoff);
#pragma unroll
                for (int np = 0; np < 4; np++) ldsm4(bf[nxt][np], ko + boff[np]);
            }
#pragma unroll
            for (int np = 0; np < 4; np++) {
                mma16(acc[2 * np],     af[cur], bf[cur][np][0], bf[cur][np][1]);
                mma16(acc[2 * np + 1], af[cur], bf[cur][np][2], bf[cur][np][3]);
            }
        }
    }

#pragma unroll
    for (int nt = 0; nt < 8; nt++) {
        int gn = n0 + n0w + nt * 8 + 2 * tg;
        float b0v = bias[gn], b1v = bias[gn + 1];
        int gm0 = m0 + m0w + g;
        *(float2*)&out[(size_t)gm0 * EE + gn] =
            make_float2(acc[nt][0] + b0v, acc[nt][1] + b1v);
        *(float2*)&out[(size_t)(gm0 + 8) * EE + gn] =
            make_float2(acc[nt][2] + b0v, acc[nt][3] + b1v);
    }
}

// ---------------------------------------------------------------------------
// Causal flash attention (unchanged, at HMMA ceiling + schedule-optimal):
// fp16 mma + LDSM, f16x2 exp2 softmax, row-sum via ones-MMA, P in registers.
// Grid (T/128, H, B) heavy-first, 256 threads, warp tile m16 x kv64,
// 3-stage cp.async K/V ring, one __syncthreads per kv tile.
// ---------------------------------------------------------------------------
#define AT_W 36
#define QS_WORDS (128 * AT_W)       // 4608
#define KV_WORDS (64 * AT_W)        // 2304
#define STAGE_W (2 * KV_WORDS)      // 4608
#define ATT_SMEM ((QS_WORDS + 3 * STAGE_W) * 4)   // 73728 B
#define ONES_H2 0x3C003C00u

__global__ __launch_bounds__(256, 2) void attn_tc_kernel()
{
    uint32_t* sm = dyn_smem;
    const uint32_t sb = smem_u32(sm);

    const int tid = threadIdx.x;
    const int warp = tid >> 5, lane = tid & 31;
    const int g = lane >> 2, tg = lane & 3;
    const int qt = (TT / 128 - 1) - blockIdx.x;   // heavy (large qt) first
    const int h = blockIdx.y, bb = blockIdx.z;
    const int q0 = qt * 128;

    const size_t hb = (size_t)bb * HH + h;
    const __half* qp = g_q + hb * TT * DD;
    const __half* kp = g_k + hb * TT * DD;
    const __half* vp = g_v + hb * TT * DD;

#pragma unroll
    for (int i = 0; i < 4; i++) {
        int idx = i * 256 + tid;
        int row = idx >> 3, c = idx & 7;
        cp16(sb + (row * AT_W + c * 4) * 4, qp + (size_t)(q0 + row) * DD + c * 8);
    }
    cp_commit();

    auto issueKV = [&](int kt) {
        const int st = kt % 3;
        const uint32_t base = sb + (QS_WORDS + st * STAGE_W) * 4;
#pragma unroll
        for (int i = 0; i < 4; i++) {
            int idx = i * 256 + tid;
            if (idx < 512) {
                int row = idx >> 3, c = idx & 7;
                cp16(base + (row * AT_W + c * 4) * 4,
                     kp + (size_t)(kt * 64 + row) * DD + c * 8);
            } else {
                int j = idx - 512;
                int row = j >> 3, c = j & 7;
                cp16(base + (KV_WORDS + row * AT_W + c * 4) * 4,
                     vp + (size_t)(kt * 64 + row) * DD + c * 8);
            }
        }
        cp_commit();
    };

    const int kt_end = 2 * qt + 1;
    issueKV(0);
    issueKV(1);

    cp_wait<2>();
    __syncthreads();

    const int mt = lane >> 3, mr = lane & 7;
    uint32_t qf[4][4];
    {
        const uint32_t qrow = sb + ((warp * 16 + (mt & 1) * 8 + mr) * AT_W) * 4;
#pragma unroll
        for (int c = 0; c < 4; c++)
            ldsm4(qf[c], qrow + (c * 8 + (mt >> 1) * 4) * 4);
    }
    uint32_t bofs[4];
#pragma unroll
    for (int np = 0; np < 4; np++)
        bofs[np] = ((np * 16 + (mt >> 1) * 8 + mr) * AT_W + (mt & 1) * 4) * 4;
    uint32_t vofs[4];
#pragma unroll
    for (int np = 0; np < 4; np++)
        vofs[np] = (((mt & 1) * 8 + mr) * AT_W + np * 8 + (mt >> 1) * 4) * 4;

    float o[8][4];
    float osum[4] = {0.f, 0.f, 0.f, 0.f};
    float m0_ = -1e30f, m1_ = -1e30f;
#pragma unroll
    for (int nt = 0; nt < 8; nt++)
#pragma unroll
        for (int j = 0; j < 4; j++) o[nt][j] = 0.f;

    for (int kt = 0; kt <= kt_end; kt++) {
        if (kt + 1 <= kt_end) cp_wait<1>(); else cp_wait<0>();
        __syncthreads();
        if (kt + 2 <= kt_end) issueKV(kt + 2);

        const uint32_t kbase = sb + (QS_WORDS + (kt % 3) * STAGE_W) * 4;
        const uint32_t vbase = kbase + KV_WORDS * 4;

        float s[8][4];
#pragma unroll
        for (int nt = 0; nt < 8; nt++)
#pragma unroll
            for (int j = 0; j < 4; j++) s[nt][j] = 0.f;
#pragma unroll
        for (int c = 0; c < 4; c++) {
            uint32_t bf[4][4];
#pragma unroll
            for (int np = 0; np < 4; np++) ldsm4(bf[np], kbase + bofs[np] + c * 32);
#pragma unroll
            for (int np = 0; np < 4; np++) {
                mma16(s[2 * np],     qf[c], bf[np][0], bf[np][1]);
                mma16(s[2 * np + 1], qf[c], bf[np][2], bf[np][3]);
            }
        }

        if (kt >= 2 * qt) {
            int row0 = q0 + warp * 16 + g;
#pragma unroll
            for (int nt = 0; nt < 8; nt++) {
                int col = kt * 64 + nt * 8 + 2 * tg;
                if (col > row0)     s[nt][0] = -1e30f;
                if (col + 1 > row0) s[nt][1] = -1e30f;
                if (col > row0 + 8)     s[nt][2] = -1e30f;
                if (col + 1 > row0 + 8) s[nt][3] = -1e30f;
            }
        }

        float mx0 = -1e30f, mx1 = -1e30f;
#pragma unroll
        for (int nt = 0; nt < 8; nt++) {
            mx0 = fmaxf(mx0, fmaxf(s[nt][0], s[nt][1]));
            mx1 = fmaxf(mx1, fmaxf(s[nt][2], s[nt][3]));
        }
        mx0 = fmaxf(mx0, __shfl_xor_sync(0xffffffffu, mx0, 1));
        mx0 = fmaxf(mx0, __shfl_xor_sync(0xffffffffu, mx0, 2));
        mx1 = fmaxf(mx1, __shfl_xor_sync(0xffffffffu, mx1, 1));
        mx1 = fmaxf(mx1, __shfl_xor_sync(0xffffffffu, mx1, 2));
        float mn0 = fmaxf(m0_, mx0), mn1 = fmaxf(m1_, mx1);
        float f0 = exp2f(m0_ - mn0), f1 = exp2f(m1_ - mn1);
        m0_ = mn0; m1_ = mn1;

        uint32_t pe[8][2];
#pragma unroll
        for (int nt = 0; nt < 8; nt++) {
            pe[nt][0] = ex2_h2(packh2(s[nt][0] - mn0, s[nt][1] - mn0));
            pe[nt][1] = ex2_h2(packh2(s[nt][2] - mn1, s[nt][3] - mn1));
        }

#pragma unroll
        for (int nt = 0; nt < 8; nt++) {
            o[nt][0] *= f0; o[nt][1] *= f0;
            o[nt][2] *= f1; o[nt][3] *= f1;
        }
        osum[0] *= f0; osum[1] *= f0; osum[2] *= f1; osum[3] *= f1;

#pragma unroll
        for (int c = 0; c < 4; c++) {
            uint32_t pa[4] = { pe[2 * c][0], pe[2 * c][1],
                               pe[2 * c + 1][0], pe[2 * c + 1][1] };
            mma16(osum, pa, ONES_H2, ONES_H2);
            uint32_t bf[4][4];
#pragma unroll
            for (int np = 0; np < 4; np++)
                ldsm4t(bf[np], vbase + vofs[np] + c * 16 * AT_W * 4);
#pragma unroll
            for (int np = 0; np < 4; np++) {
                mma16(o[2 * np],     pa, bf[np][0], bf[np][1]);
                mma16(o[2 * np + 1], pa, bf[np][2], bf[np][3]);
            }
        }
    }

    float inv0 = 1.f / osum[0], inv1 = 1.f / osum[2];
    int t0 = q0 + warp * 16 + g;
#pragma unroll
    for (int nt = 0; nt < 8; nt++) {
        int col = h * 64 + nt * 8 + 2 * tg;
        *(__half2*)&g_y[((size_t)bb * TT + t0) * EE + col] =
            __floats2half2_rn(o[nt][0] * inv0, o[nt][1] * inv0);
        *(__half2*)&g_y[((size_t)bb * TT + t0 + 8) * EE + col] =
            __floats2half2_rn(o[nt][2] * inv1, o[nt][3] * inv1);
    }
}

// ---------------------------------------------------------------------------
extern "C" void kernel_launch(void* const* d_in, const int* in_sizes, int n_in,
                              void* d_out, int out_size)
{
    (void)in_sizes; (void)n_in; (void)out_size;
    const float* x      = (const float*)d_in[0];
    const float* W_attn = (const float*)d_in[1];
    const float* b_attn = (const float*)d_in[2];
    const float* W_proj = (const float*)d_in[3];
    const float* b_proj = (const float*)d_in[4];
    float* out = (float*)d_out;

    __half *xt, *wta, *wtp, *yv;
    cudaGetSymbolAddress((void**)&xt, g_xt);
    cudaGetSymbolAddress((void**)&wta, g_wta);
    cudaGetSymbolAddress((void**)&wtp, g_wtp);
    cudaGetSymbolAddress((void**)&yv, g_y);

    // 0) One merged prep launch: X->half, both weight transposes
    prep_kernel<<<PREP_BLOCKS, 256>>>(x, W_attn, W_proj, xt, wta, wtp);

    // 1) QKV projection (BM128xBN256, BK=128, 2-stage) -> g_q/g_k/g_v
    cudaFuncSetAttribute(qkv_gemm_kernel,
                         cudaFuncAttributeMaxDynamicSharedMemorySize, QKV_SMEM);
    qkv_gemm_kernel<<<dim3(N_QKV / 256, MM / 128), 512, QKV_SMEM>>>(
        xt, wta, b_attn);

    // 2) Causal flash attention -> g_y
    cudaFuncSetAttribute(attn_tc_kernel,
                         cudaFuncAttributeMaxDynamicSharedMemorySize, ATT_SMEM);
    attn_tc_kernel<<<dim3(TT / 128, HH, BB), 256, ATT_SMEM>>>();

    // 3) Output projection (BM128xBN128) -> d_out (fp32)
    cudaFuncSetAttribute(proj_gemm_kernel,
                         cudaFuncAttributeMaxDynamicSharedMemorySize, PROJ_SMEM);
    proj_gemm_kernel<<<dim3(EE / 128, MM / 128), 512, PROJ_SMEM>>>(
        yv, wtp, b_proj, out);
}

// round 17
// speedup vs baseline: 1.0782x; 1.0782x over previous
#include <cuda_runtime.h>
#include <cuda_fp16.h>
#include <cstdint>

// Problem constants
#define BB 2
#define TT 4096
#define EE 768
#define HH 12
#define DD 64
#define MM (BB * TT)        // 8192
#define N_QKV (3 * EE)      // 2304
#define KTOT 768
#define LOG2E 1.4426950408889634f

// Scratch (allocation-free rule: __device__ globals), all fp16
__device__ __half g_q[(size_t)BB * HH * TT * DD];   // [B,H,T,D], scaled 0.125*log2e
__device__ __half g_k[(size_t)BB * HH * TT * DD];   // [B,H,T,D]
__device__ __half g_v[(size_t)BB * HH * TT * DD];   // [B,H,T,D]
__device__ __half g_y[(size_t)BB * TT * EE];        // [B,T,E]
__device__ __half g_xt[(size_t)MM * EE];            // X as half
__device__ __half g_wta[(size_t)N_QKV * EE];        // W_attn^T [2304][768]
__device__ __half g_wtp[(size_t)EE * EE];           // W_proj^T [768][768]

// ---------------------------------------------------------------------------
// Helpers
// ---------------------------------------------------------------------------
__device__ __forceinline__ uint32_t smem_u32(const void* p) {
    uint32_t a;
    asm("{ .reg .u64 t; cvta.to.shared.u64 t, %1; cvt.u32.u64 %0, t; }"
        : "=r"(a) : "l"(p));
    return a;
}
__device__ __forceinline__ void cp16(uint32_t dst, const void* src) {
    asm volatile("cp.async.cg.shared.global [%0], [%1], 16;"
                 :: "r"(dst), "l"(src) : "memory");
}
__device__ __forceinline__ void cp_commit() {
    asm volatile("cp.async.commit_group;" ::: "memory");
}
template<int N> __device__ __forceinline__ void cp_wait() {
    asm volatile("cp.async.wait_group %0;" :: "n"(N) : "memory");
}
__device__ __forceinline__ uint32_t packh2(float a, float b) {
    __half2 h = __floats2half2_rn(a, b);
    return *(uint32_t*)&h;
}
__device__ __forceinline__ uint32_t ex2_h2(uint32_t x) {   // 2x half exp2, 1 MUFU
    uint32_t r;
    asm("ex2.approx.f16x2 %0, %1;" : "=r"(r) : "r"(x));
    return r;
}
// ldmatrix x4: four 8x8 b16 mats; lane l addresses row l%8 of mat l/8.
__device__ __forceinline__ void ldsm4(uint32_t* r, uint32_t addr) {
    asm volatile("ldmatrix.sync.aligned.m8n8.x4.shared.b16 {%0,%1,%2,%3}, [%4];"
                 : "=r"(r[0]), "=r"(r[1]), "=r"(r[2]), "=r"(r[3]) : "r"(addr));
}
// transposed variant: fragment = transpose of each stored 8x8 (b16)
__device__ __forceinline__ void ldsm4t(uint32_t* r, uint32_t addr) {
    asm volatile("ldmatrix.sync.aligned.m8n8.x4.trans.shared.b16 {%0,%1,%2,%3}, [%4];"
                 : "=r"(r[0]), "=r"(r[1]), "=r"(r[2]), "=r"(r[3]) : "r"(addr));
}

// mma.sync m16n8k16 f16 -> f32.
__device__ __forceinline__ void mma16(float* c, const uint32_t* a,
                                      uint32_t b0, uint32_t b1) {
    asm volatile(
        "mma.sync.aligned.m16n8k16.row.col.f32.f16.f16.f32 "
        "{%0,%1,%2,%3}, {%4,%5,%6,%7}, {%8,%9}, {%0,%1,%2,%3};\n"
        : "+f"(c[0]), "+f"(c[1]), "+f"(c[2]), "+f"(c[3])
        : "r"(a[0]), "r"(a[1]), "r"(a[2]), "r"(a[3]), "r"(b0), "r"(b1));
}

extern __shared__ uint32_t dyn_smem[];

// ---------------------------------------------------------------------------
// Merged prep kernel: one launch does X-convert + both weight transposes.
// Blocks [0, 3072): cvt X.  [3072, 4800): transpose W_attn.  [4800, 5376):
// transpose W_proj.  256 threads everywhere.
// ---------------------------------------------------------------------------
#define PREP_X_BLOCKS ((MM * EE) / (256 * 8))                 // 3072
#define PREP_WA_BLOCKS ((N_QKV / 32) * (EE / 32))             // 1728
#define PREP_WP_BLOCKS ((EE / 32) * (EE / 32))                // 576
#define PREP_BLOCKS (PREP_X_BLOCKS + PREP_WA_BLOCKS + PREP_WP_BLOCKS)

__global__ __launch_bounds__(256) void prep_kernel(
    const float* __restrict__ x, const float* __restrict__ Wa,
    const float* __restrict__ Wp,
    __half* __restrict__ xt, __half* __restrict__ wta, __half* __restrict__ wtp)
{
    __shared__ float t[32][33];
    const int bx = blockIdx.x;
    if (bx < PREP_X_BLOCKS) {
        size_t i = ((size_t)bx * 256 + threadIdx.x) * 8;
        float4 v0 = *(const float4*)&x[i];
        float4 v1 = *(const float4*)&x[i + 4];
        uint4 o;
        o.x = packh2(v0.x, v0.y);
        o.y = packh2(v0.z, v0.w);
        o.z = packh2(v1.x, v1.y);
        o.w = packh2(v1.z, v1.w);
        *(uint4*)&xt[i] = o;
        return;
    }
    // transpose branch: dst[n][k] = half(src[k][n])
    const float* src;
    __half* dst;
    int K, N, tb;
    if (bx < PREP_X_BLOCKS + PREP_WA_BLOCKS) {
        tb = bx - PREP_X_BLOCKS; src = Wa; dst = wta; K = EE; N = N_QKV;
    } else {
        tb = bx - PREP_X_BLOCKS - PREP_WA_BLOCKS; src = Wp; dst = wtp; K = EE; N = EE;
    }
    const int nblk = N / 32;
    const int n0 = (tb % nblk) * 32, k0 = (tb / nblk) * 32;
    const int tx = threadIdx.x & 31, ty = threadIdx.x >> 5;   // 32 x 8
#pragma unroll
    for (int j = 0; j < 4; j++)
        t[ty + j * 8][tx] = src[(size_t)(k0 + ty + j * 8) * N + n0 + tx];
    __syncthreads();
#pragma unroll
    for (int j = 0; j < 4; j++)
        dst[(size_t)(n0 + ty + j * 8) * K + k0 + tx] =
            __float2half_rn(t[tx][ty + j * 8]);
}

// ---------------------------------------------------------------------------
// QKV GEMM (best measured config, R11/R13): BM128 x BN256, BK=64, 512
// threads = 16 warps in 4x4 grid of m32 x n64 tiles.  3-stage cp.async
// single-sync pipeline + register-level LDSM double buffering.  Epilogue
// staged through smem for coalesced q/k/v scatter (q scaled 0.125*log2e).
// ---------------------------------------------------------------------------
#define BKH 64
#define NKT (KTOT / BKH)        // 12
#define TILE_W 36
#define QA_WORDS (128 * TILE_W)             // 4608
#define QB_WORDS (256 * TILE_W)             // 9216
#define QSTAGE_WORDS (QA_WORDS + QB_WORDS)  // 13824
#define QKV_SMEM (3 * QSTAGE_WORDS * 4)     // 165888 B
#define CS_HW 264

__global__ __launch_bounds__(512, 1) void qkv_gemm_kernel(
    const __half* __restrict__ A, const __half* __restrict__ Bt,
    const float* __restrict__ bias)
{
    uint32_t* sm = dyn_smem;
    const uint32_t sb = smem_u32(sm);
    const int tid = threadIdx.x;
    const int warp = tid >> 5, lane = tid & 31;
    const int g = lane >> 2, tg = lane & 3;
    const int wm = warp >> 2, wn = warp & 3;      // 4 x 4 warp grid
    const int m0 = blockIdx.y * 128, n0 = blockIdx.x * 256;
    const int m0w = wm * 32, n0w = wn * 64;

    const int lrA = tid >> 2;
    const int cbA = (tid & 3) * 2;
    const int lrB = tid >> 1;
    const int cbB = (tid & 1) * 4;
    const __half* asrc0 = A + (size_t)(m0 + lrA) * KTOT + cbA * 8;
    const __half* bsrc0 = Bt + (size_t)(n0 + lrB) * KTOT + cbB * 8;
    const uint32_t adst0 = sb + (lrA * TILE_W + cbA * 4) * 4;
    const uint32_t bdst0 = sb + (QA_WORDS + lrB * TILE_W + cbB * 4) * 4;

    const int mt = lane >> 3, mr = lane & 7;
    uint32_t aoff[2];
#pragma unroll
    for (int mi = 0; mi < 2; mi++)
        aoff[mi] = ((m0w + mi * 16 + (mt & 1) * 8 + mr) * TILE_W + (mt >> 1) * 4) * 4;
    uint32_t boff[4];
#pragma unroll
    for (int np = 0; np < 4; np++)
        boff[np] = (QA_WORDS + (n0w + np * 16 + (mt >> 1) * 8 + mr) * TILE_W
                    + (mt & 1) * 4) * 4;

    float acc[2][8][4];
#pragma unroll
    for (int mi = 0; mi < 2; mi++)
#pragma unroll
        for (int nt = 0; nt < 8; nt++)
#pragma unroll
            for (int j = 0; j < 4; j++) acc[mi][nt][j] = 0.f;

    auto issue = [&](int i) {
        const int s = i % 3;
        const int k0 = i * BKH;
        const uint32_t so = (uint32_t)(s * QSTAGE_WORDS * 4);
        cp16(adst0 + so,      asrc0 + k0);
        cp16(adst0 + so + 16, asrc0 + k0 + 8);
#pragma unroll
        for (int j = 0; j < 4; j++)
            cp16(bdst0 + so + j * 16, bsrc0 + k0 + j * 8);
        cp_commit();
    };

    issue(0);
    issue(1);
    for (int i = 0; i < NKT; i++) {
        if (i + 1 < NKT) cp_wait<1>(); else cp_wait<0>();
        __syncthreads();
        if (i + 2 < NKT) issue(i + 2);

        const uint32_t soff = sb + (uint32_t)((i % 3) * QSTAGE_WORDS * 4);
        uint32_t af[2][2][4], bf[2][4][4];
        ldsm4(af[0][0], soff + aoff[0]);
        ldsm4(af[0][1], soff + aoff[1]);
#pragma unroll
        for (int np = 0; np < 4; np++) ldsm4(bf[0][np], soff + boff[np]);
#pragma unroll
        for (int ks = 0; ks < 4; ks++) {
            const int cur = ks & 1, nxt = cur ^ 1;
            if (ks < 3) {
                const uint32_t ko = soff + (ks + 1) * 32;
                ldsm4(af[nxt][0], ko + aoff[0]);
                ldsm4(af[nxt][1], ko + aoff[1]);
#pragma unroll
                for (int np = 0; np < 4; np++) ldsm4(bf[nxt][np], ko + boff[np]);
            }
#pragma unroll
            for (int np = 0; np < 4; np++) {
                mma16(acc[0][2 * np],     af[cur][0], bf[cur][np][0], bf[cur][np][1]);
                mma16(acc[0][2 * np + 1], af[cur][0], bf[cur][np][2], bf[cur][np][3]);
                mma16(acc[1][2 * np],     af[cur][1], bf[cur][np][0], bf[cur][np][1]);
                mma16(acc[1][2 * np + 1], af[cur][1], bf[cur][np][2], bf[cur][np][3]);
            }
        }
    }

    // Epilogue: stage C to smem (half, bias+scale), then coalesced scatter.
    __half* Cs = (__half*)sm;
    __syncthreads();
#pragma unroll
    for (int mi = 0; mi < 2; mi++)
#pragma unroll
        for (int hi = 0; hi < 2; hi++) {
            int lrow = m0w + mi * 16 + hi * 8 + g;
#pragma unroll
            for (int nt = 0; nt < 8; nt++) {
                int lcol = n0w + nt * 8 + 2 * tg;
                int gn = n0 + lcol;
                float v0 = acc[mi][nt][hi * 2] + bias[gn];
                float v1 = acc[mi][nt][hi * 2 + 1] + bias[gn + 1];
                float sc = (gn < EE) ? (0.125f * LOG2E) : 1.0f;
                *(__half2*)&Cs[lrow * CS_HW + lcol] =
                    __floats2half2_rn(v0 * sc, v1 * sc);
            }
        }
    __syncthreads();
#pragma unroll
    for (int it = 0; it < 8; it++) {
        int c = it * 512 + tid;            // 0..4095
        int row = c >> 5, seg = c & 31;
        uint4 v = *(uint4*)&Cs[row * CS_HW + seg * 8];
        int gm = m0 + row, gn = n0 + seg * 8;
        int bbv = gm >> 12, t = gm & (TT - 1);
        int part = gn / EE;
        int rem = gn - part * EE;
        int hh = rem >> 6, d = rem & 63;
        __half* dst = (part == 0) ? g_q : ((part == 1) ? g_k : g_v);
        *(uint4*)&dst[(((size_t)bbv * HH + hh) * TT + t) * DD + d] = v;
    }
}

// ---------------------------------------------------------------------------
// Output projection GEMM (best measured config, R9/R13): BM128 x BN128,
// BK=64, 512 threads = 16 warps in 8x2 grid of m16 x n64 tiles (384 blocks,
// good wave quantization).  3-stage pipeline + reg double buffering.
// ---------------------------------------------------------------------------
#define PHALF_ST (128 * TILE_W)             // 4608 words per A or B buffer
#define PSTAGE_WORDS (2 * PHALF_ST)         // 9216
#define PROJ_SMEM (3 * PSTAGE_WORDS * 4)    // 110592 B

__global__ __launch_bounds__(512, 1) void proj_gemm_kernel(
    const __half* __restrict__ A, const __half* __restrict__ Bt,
    const float* __restrict__ bias, float* __restrict__ out)
{
    uint32_t* sm = dyn_smem;
    const uint32_t sb = smem_u32(sm);
    const int tid = threadIdx.x;
    const int warp = tid >> 5, lane = tid & 31;
    const int g = lane >> 2, tg = lane & 3;
    const int wm = warp >> 1, wn = warp & 1;      // 8 x 2 warp grid
    const int m0 = blockIdx.y * 128, n0 = blockIdx.x * 128;
    const int m0w = wm * 16, n0w = wn * 64;

    const int lr = tid >> 2;
    const int cb = (tid & 3) * 2;
    const __half* asrc0 = A + (size_t)(m0 + lr) * KTOT + cb * 8;
    const __half* bsrc0 = Bt + (size_t)(n0 + lr) * KTOT + cb * 8;
    const uint32_t adst0 = sb + (lr * TILE_W + cb * 4) * 4;
    const uint32_t bdst0 = sb + (PHALF_ST + lr * TILE_W + cb * 4) * 4;

    const int mt = lane >> 3, mr = lane & 7;
    const uint32_t aoff =
        ((m0w + (mt & 1) * 8 + mr) * TILE_W + (mt >> 1) * 4) * 4;
    uint32_t boff[4];
#pragma unroll
    for (int np = 0; np < 4; np++)
        boff[np] = (PHALF_ST + (n0w + np * 16 + (mt >> 1) * 8 + mr) * TILE_W
                    + (mt & 1) * 4) * 4;

    float acc[8][4];
#pragma unroll
    for (int nt = 0; nt < 8; nt++)
#pragma unroll
        for (int j = 0; j < 4; j++) acc[nt][j] = 0.f;

    auto issue = [&](int i) {
        const int s = i % 3;
        const int k0 = i * BKH;
        const uint32_t so = (uint32_t)(s * PSTAGE_WORDS * 4);
        cp16(adst0 + so,      asrc0 + k0);
        cp16(adst0 + so + 16, asrc0 + k0 + 8);
        cp16(bdst0 + so,      bsrc0 + k0);
        cp16(bdst0 + so + 16, bsrc0 + k0 + 8);
        cp_commit();
    };

    issue(0);
    issue(1);
    for (int i = 0; i < NKT; i++) {
        if (i + 1 < NKT) cp_wait<1>(); else cp_wait<0>();
        __syncthreads();
        if (i + 2 < NKT) issue(i + 2);

        const uint32_t soff = sb + (uint32_t)((i % 3) * PSTAGE_WORDS * 4);
        uint32_t af[2][4], bf[2][4][4];
        ldsm4(af[0], soff + aoff);
#pragma unroll
        for (int np = 0; np < 4; np++) ldsm4(bf[0][np], soff + boff[np]);
#pragma unroll
        for (int ks = 0; ks < 4; ks++) {
            const int cur = ks & 1, nxt = cur ^ 1;
            if (ks < 3) {
                const uint32_t ko = soff + (ks + 1) * 32;
                ldsm4(af[nxt], ko + aoff);
#pragma unroll
                for (int np = 0; np < 4; np++) ldsm4(bf[nxt][np], ko + boff[np]);
            }
#pragma unroll
            for (int np = 0; np < 4; np++) {
                mma16(acc[2 * np],     af[cur], bf[cur][np][0], bf[cur][np][1]);
                mma16(acc[2 * np + 1], af[cur], bf[cur][np][2], bf[cur][np][3]);
            }
        }
    }

#pragma unroll
    for (int nt = 0; nt < 8; nt++) {
        int gn = n0 + n0w + nt * 8 + 2 * tg;
        float b0v = bias[gn], b1v = bias[gn + 1];
        int gm0 = m0 + m0w + g;
        *(float2*)&out[(size_t)gm0 * EE + gn] =
            make_float2(acc[nt][0] + b0v, acc[nt][1] + b1v);
        *(float2*)&out[(size_t)(gm0 + 8) * EE + gn] =
            make_float2(acc[nt][2] + b0v, acc[nt][3] + b1v);
    }
}

// ---------------------------------------------------------------------------
// Causal flash attention (unchanged, at HMMA ceiling + schedule-optimal):
// fp16 mma + LDSM, f16x2 exp2 softmax, row-sum via ones-MMA, P in registers.
// Grid (T/128, H, B) heavy-first, 256 threads, warp tile m16 x kv64,
// 3-stage cp.async K/V ring, one __syncthreads per kv tile.
// ---------------------------------------------------------------------------
#define AT_W 36
#define QS_WORDS (128 * AT_W)       // 4608
#define KV_WORDS (64 * AT_W)        // 2304
#define STAGE_W (2 * KV_WORDS)      // 4608
#define ATT_SMEM ((QS_WORDS + 3 * STAGE_W) * 4)   // 73728 B
#define ONES_H2 0x3C003C00u

__global__ __launch_bounds__(256, 2) void attn_tc_kernel()
{
    uint32_t* sm = dyn_smem;
    const uint32_t sb = smem_u32(sm);

    const int tid = threadIdx.x;
    const int warp = tid >> 5, lane = tid & 31;
    const int g = lane >> 2, tg = lane & 3;
    const int qt = (TT / 128 - 1) - blockIdx.x;   // heavy (large qt) first
    const int h = blockIdx.y, bb = blockIdx.z;
    const int q0 = qt * 128;

    const size_t hb = (size_t)bb * HH + h;
    const __half* qp = g_q + hb * TT * DD;
    const __half* kp = g_k + hb * TT * DD;
    const __half* vp = g_v + hb * TT * DD;

#pragma unroll
    for (int i = 0; i < 4; i++) {
        int idx = i * 256 + tid;
        int row = idx >> 3, c = idx & 7;
        cp16(sb + (row * AT_W + c * 4) * 4, qp + (size_t)(q0 + row) * DD + c * 8);
    }
    cp_commit();

    auto issueKV = [&](int kt) {
        const int st = kt % 3;
        const uint32_t base = sb + (QS_WORDS + st * STAGE_W) * 4;
#pragma unroll
        for (int i = 0; i < 4; i++) {
            int idx = i * 256 + tid;
            if (idx < 512) {
                int row = idx >> 3, c = idx & 7;
                cp16(base + (row * AT_W + c * 4) * 4,
                     kp + (size_t)(kt * 64 + row) * DD + c * 8);
            } else {
                int j = idx - 512;
                int row = j >> 3, c = j & 7;
                cp16(base + (KV_WORDS + row * AT_W + c * 4) * 4,
                     vp + (size_t)(kt * 64 + row) * DD + c * 8);
            }
        }
        cp_commit();
    };

    const int kt_end = 2 * qt + 1;
    issueKV(0);
    issueKV(1);

    cp_wait<2>();
    __syncthreads();

    const int mt = lane >> 3, mr = lane & 7;
    uint32_t qf[4][4];
    {
        const uint32_t qrow = sb + ((warp * 16 + (mt & 1) * 8 + mr) * AT_W) * 4;
#pragma unroll
        for (int c = 0; c < 4; c++)
            ldsm4(qf[c], qrow + (c * 8 + (mt >> 1) * 4) * 4);
    }
    uint32_t bofs[4];
#pragma unroll
    for (int np = 0; np < 4; np++)
        bofs[np] = ((np * 16 + (mt >> 1) * 8 + mr) * AT_W + (mt & 1) * 4) * 4;
    uint32_t vofs[4];
#pragma unroll
    for (int np = 0; np < 4; np++)
        vofs[np] = (((mt & 1) * 8 + mr) * AT_W + np * 8 + (mt >> 1) * 4) * 4;

    float o[8][4];
    float osum[4] = {0.f, 0.f, 0.f, 0.f};
    float m0_ = -1e30f, m1_ = -1e30f;
#pragma unroll
    for (int nt = 0; nt < 8; nt++)
#pragma unroll
        for (int j = 0; j < 4; j++) o[nt][j] = 0.f;

    for (int kt = 0; kt <= kt_end; kt++) {
        if (kt + 1 <= kt_end) cp_wait<1>(); else cp_wait<0>();
        __syncthreads();
        if (kt + 2 <= kt_end) issueKV(kt + 2);

        const uint32_t kbase = sb + (QS_WORDS + (kt % 3) * STAGE_W) * 4;
        const uint32_t vbase = kbase + KV_WORDS * 4;

        float s[8][4];
#pragma unroll
        for (int nt = 0; nt < 8; nt++)
#pragma unroll
            for (int j = 0; j < 4; j++) s[nt][j] = 0.f;
#pragma unroll
        for (int c = 0; c < 4; c++) {
            uint32_t bf[4][4];
#pragma unroll
            for (int np = 0; np < 4; np++) ldsm4(bf[np], kbase + bofs[np] + c * 32);
#pragma unroll
            for (int np = 0; np < 4; np++) {
                mma16(s[2 * np],     qf[c], bf[np][0], bf[np][1]);
                mma16(s[2 * np + 1], qf[c], bf[np][2], bf[np][3]);
            }
        }

        if (kt >= 2 * qt) {
            int row0 = q0 + warp * 16 + g;
#pragma unroll
            for (int nt = 0; nt < 8; nt++) {
                int col = kt * 64 + nt * 8 + 2 * tg;
                if (col > row0)     s[nt][0] = -1e30f;
                if (col + 1 > row0) s[nt][1] = -1e30f;
                if (col > row0 + 8)     s[nt][2] = -1e30f;
                if (col + 1 > row0 + 8) s[nt][3] = -1e30f;
            }
        }

        float mx0 = -1e30f, mx1 = -1e30f;
#pragma unroll
        for (int nt = 0; nt < 8; nt++) {
            mx0 = fmaxf(mx0, fmaxf(s[nt][0], s[nt][1]));
            mx1 = fmaxf(mx1, fmaxf(s[nt][2], s[nt][3]));
        }
        mx0 = fmaxf(mx0, __shfl_xor_sync(0xffffffffu, mx0, 1));
        mx0 = fmaxf(mx0, __shfl_xor_sync(0xffffffffu, mx0, 2));
        mx1 = fmaxf(mx1, __shfl_xor_sync(0xffffffffu, mx1, 1));
        mx1 = fmaxf(mx1, __shfl_xor_sync(0xffffffffu, mx1, 2));
        float mn0 = fmaxf(m0_, mx0), mn1 = fmaxf(m1_, mx1);
        float f0 = exp2f(m0_ - mn0), f1 = exp2f(m1_ - mn1);
        m0_ = mn0; m1_ = mn1;

        uint32_t pe[8][2];
#pragma unroll
        for (int nt = 0; nt < 8; nt++) {
            pe[nt][0] = ex2_h2(packh2(s[nt][0] - mn0, s[nt][1] - mn0));
            pe[nt][1] = ex2_h2(packh2(s[nt][2] - mn1, s[nt][3] - mn1));
        }

#pragma unroll
        for (int nt = 0; nt < 8; nt++) {
            o[nt][0] *= f0; o[nt][1] *= f0;
            o[nt][2] *= f1; o[nt][3] *= f1;
        }
        osum[0] *= f0; osum[1] *= f0; osum[2] *= f1; osum[3] *= f1;

#pragma unroll
        for (int c = 0; c < 4; c++) {
            uint32_t pa[4] = { pe[2 * c][0], pe[2 * c][1],
                               pe[2 * c + 1][0], pe[2 * c + 1][1] };
            mma16(osum, pa, ONES_H2, ONES_H2);
            uint32_t bf[4][4];
#pragma unroll
            for (int np = 0; np < 4; np++)
                ldsm4t(bf[np], vbase + vofs[np] + c * 16 * AT_W * 4);
#pragma unroll
            for (int np = 0; np < 4; np++) {
                mma16(o[2 * np],     pa, bf[np][0], bf[np][1]);
                mma16(o[2 * np + 1], pa, bf[np][2], bf[np][3]);
            }
        }
    }

    float inv0 = 1.f / osum[0], inv1 = 1.f / osum[2];
    int t0 = q0 + warp * 16 + g;
#pragma unroll
    for (int nt = 0; nt < 8; nt++) {
        int col = h * 64 + nt * 8 + 2 * tg;
        *(__half2*)&g_y[((size_t)bb * TT + t0) * EE + col] =
            __floats2half2_rn(o[nt][0] * inv0, o[nt][1] * inv0);
        *(__half2*)&g_y[((size_t)bb * TT + t0 + 8) * EE + col] =
            __floats2half2_rn(o[nt][2] * inv1, o[nt][3] * inv1);
    }
}

// ---------------------------------------------------------------------------
extern "C" void kernel_launch(void* const* d_in, const int* in_sizes, int n_in,
                              void* d_out, int out_size)
{
    (void)in_sizes; (void)n_in; (void)out_size;
    const float* x      = (const float*)d_in[0];
    const float* W_attn = (const float*)d_in[1];
    const float* b_attn = (const float*)d_in[2];
    const float* W_proj = (const float*)d_in[3];
    const float* b_proj = (const float*)d_in[4];
    float* out = (float*)d_out;

    __half *xt, *wta, *wtp, *yv;
    cudaGetSymbolAddress((void**)&xt, g_xt);
    cudaGetSymbolAddress((void**)&wta, g_wta);
    cudaGetSymbolAddress((void**)&wtp, g_wtp);
    cudaGetSymbolAddress((void**)&yv, g_y);

    // 0) One merged prep launch: X->half, both weight transposes
    prep_kernel<<<PREP_BLOCKS, 256>>>(x, W_attn, W_proj, xt, wta, wtp);

    // 1) QKV projection (BM128xBN256, BK=64, 3-stage) -> g_q/g_k/g_v
    cudaFuncSetAttribute(qkv_gemm_kernel,
                         cudaFuncAttributeMaxDynamicSharedMemorySize, QKV_SMEM);
    qkv_gemm_kernel<<<dim3(N_QKV / 256, MM / 128), 512, QKV_SMEM>>>(
        xt, wta, b_attn);

    // 2) Causal flash attention -> g_y
    cudaFuncSetAttribute(attn_tc_kernel,
                         cudaFuncAttributeMaxDynamicSharedMemorySize, ATT_SMEM);
    attn_tc_kernel<<<dim3(TT / 128, HH, BB), 256, ATT_SMEM>>>();

    // 3) Output projection (BM128xBN128) -> d_out (fp32)
    cudaFuncSetAttribute(proj_gemm_kernel,
                         cudaFuncAttributeMaxDynamicSharedMemorySize, PROJ_SMEM);
    proj_gemm_kernel<<<dim3(EE / 128, MM / 128), 512, PROJ_SMEM>>>(
        yv, wtp, b_proj, out);
}